// round 1
// baseline (speedup 1.0000x reference)
#include <cuda_runtime.h>
#include <math.h>

// BuildingModule: 3-state RC thermal network, serial scan over T=1024 steps,
// B=8192 independent chains. One thread per chain; 8-step chunks with
// 256-bit vector ld/st and register double-buffering of u.

#define BATCH   8192
#define TSTEPS  1024
#define CHUNK   8
#define NCHUNK  (TSTEPS / CHUNK)   // 128

struct __align__(32) f8 { float v[8]; };

__device__ __forceinline__ f8 ldg256(const float* p) {
    f8 r;
    asm volatile("ld.global.nc.v8.f32 {%0,%1,%2,%3,%4,%5,%6,%7}, [%8];"
        : "=f"(r.v[0]), "=f"(r.v[1]), "=f"(r.v[2]), "=f"(r.v[3]),
          "=f"(r.v[4]), "=f"(r.v[5]), "=f"(r.v[6]), "=f"(r.v[7])
        : "l"(p));
    return r;
}

__device__ __forceinline__ void stg256(float* p, const float* s) {
    asm volatile("st.global.v8.f32 [%0], {%1,%2,%3,%4,%5,%6,%7,%8};"
        :: "l"(p),
           "f"(s[0]), "f"(s[1]), "f"(s[2]), "f"(s[3]),
           "f"(s[4]), "f"(s[5]), "f"(s[6]), "f"(s[7])
        : "memory");
}

__device__ __forceinline__ float rcpa(float x) {
    float y; asm("rcp.approx.ftz.f32 %0, %1;" : "=f"(y) : "f"(x)); return y;
}
__device__ __forceinline__ float ex2a(float x) {
    float y; asm("ex2.approx.ftz.f32 %0, %1;" : "=f"(y) : "f"(x)); return y;
}

__global__ void __launch_bounds__(32)
bm_kernel(const float* __restrict__ x0g,
          const float* __restrict__ ug,
          const float* __restrict__ lamg,
          float* __restrict__ outg)
{
    const int b = blockIdx.x * 32 + threadIdx.x;

    // e = exp(lam): 14 broadcast scalars, precise expf once.
    const float e12 = expf(lamg[0]);
    const float e23 = expf(lamg[1]);
    const float ee0 = expf(lamg[2]),  ee1 = expf(lamg[3]),  ee2 = expf(lamg[4]);
    const float es0 = expf(lamg[5]),  es1 = expf(lamg[6]),  es2 = expf(lamg[7]);
    const float eh0 = expf(lamg[8]),  eh1 = expf(lamg[9]),  eh2 = expf(lamg[10]);
    const float ec0 = expf(lamg[11]), ec1 = expf(lamg[12]), ec2 = expf(lamg[13]);

    // kl_c = (H / C_c) * log2(e), folded so x *= ex2(kl_c * s_c)
    const float kl0 = (float)(60.0 / 10665991.0 * 1.4426950408889634);
    const float kl1 = (float)(60.0 / 27000000.0 * 1.4426950408889634);
    const float kl2 = (float)(60.0 /  7953253.0 * 1.4426950408889634);

    float x0 = x0g[b * 3 + 0];
    float x1 = x0g[b * 3 + 1];
    float x2 = x0g[b * 3 + 2];

    const float* up = ug   + (size_t)b * (TSTEPS * 8);
    float*       op = outg + (size_t)b * (TSTEPS * 3);

    // Prime the u double-buffer with chunk 0.
    f8 cur[CHUNK];
#pragma unroll
    for (int j = 0; j < CHUNK; j++) cur[j] = ldg256(up + j * 8);

    for (int c = 0; c < NCHUNK; c++) {
        // Prefetch next chunk while computing this one.
        f8 nxt[CHUNK];
        if (c < NCHUNK - 1) {
#pragma unroll
            for (int j = 0; j < CHUNK; j++)
                nxt[j] = ldg256(up + (size_t)(c + 1) * (CHUNK * 8) + j * 8);
        }

        float buf[CHUNK * 3];
        // Slot 8c: carry-in state (x0 for c==0, never masked there).
        {
            const bool m0 = (c != 0) && (cur[0].v[0] < 1e-6f);
            buf[0] = m0 ? -1.0f : x0;
            buf[1] = m0 ? -1.0f : x1;
            buf[2] = m0 ? -1.0f : x2;
        }

#pragma unroll
        for (int j = 0; j < CHUNK; j++) {
            const float i0 = rcpa(x0);
            const float i1 = rcpa(x1);
            const float i2 = rcpa(x2);
            const float d12 = i0 - i1;
            const float d23 = i1 - i2;
            const float t12 = e12 * d12;
            const float t23 = e23 * d23;
            const float a0 =  t12 * x1;
            const float a1 =  t23 * x2 - t12 * x0;
            const float a2 = -t23 * x1;

            const float u0 = cur[j].v[0];
            const float u1 = cur[j].v[1];
            // Bu_c = ee_c*(inv_c*u0 - 1) + es_c*u1 + eh_c*u[2+c] + ec_c*u[5+c]
            const float s0 = a0 + (ee0 * (i0 * u0) - ee0) + es0 * u1
                           + eh0 * cur[j].v[2] + ec0 * cur[j].v[5];
            const float s1 = a1 + (ee1 * (i1 * u0) - ee1) + es1 * u1
                           + eh1 * cur[j].v[3] + ec1 * cur[j].v[6];
            const float s2 = a2 + (ee2 * (i2 * u0) - ee2) + es2 * u1
                           + eh2 * cur[j].v[4] + ec2 * cur[j].v[7];

            x0 *= ex2a(kl0 * s0);
            x1 *= ex2a(kl1 * s1);
            x2 *= ex2a(kl2 * s2);

            if (j < CHUNK - 1) {
                // Slot 8c + j + 1, masked by u[b, 8c+j+1, 0] < 1e-6
                const bool m = cur[j + 1].v[0] < 1e-6f;
                buf[3 * (j + 1) + 0] = m ? -1.0f : x0;
                buf[3 * (j + 1) + 1] = m ? -1.0f : x1;
                buf[3 * (j + 1) + 2] = m ? -1.0f : x2;
            }
            // j == CHUNK-1 result becomes the carry into the next chunk's
            // slot 0 (masked there). For the final chunk the step at t=1023
            // reads valid memory but its result is never written.
        }

        float* ob = op + (size_t)c * (CHUNK * 3);  // 96B chunks, 32B aligned
        stg256(ob +  0, buf +  0);
        stg256(ob +  8, buf +  8);
        stg256(ob + 16, buf + 16);

        if (c < NCHUNK - 1) {
#pragma unroll
            for (int j = 0; j < CHUNK; j++) cur[j] = nxt[j];
        }
    }
}

extern "C" void kernel_launch(void* const* d_in, const int* in_sizes, int n_in,
                              void* d_out, int out_size)
{
    // Route inputs by size for robustness: lam=14, x0=8192*3, u=8192*1024*8.
    const float* x0  = nullptr;
    const float* u   = nullptr;
    const float* lam = nullptr;
    for (int i = 0; i < n_in; i++) {
        if (in_sizes[i] == 14)               lam = (const float*)d_in[i];
        else if (in_sizes[i] == BATCH * 3)   x0  = (const float*)d_in[i];
        else                                 u   = (const float*)d_in[i];
    }
    bm_kernel<<<BATCH / 32, 32>>>(x0, u, lam, (float*)d_out);
}